// round 3
// baseline (speedup 1.0000x reference)
#include <cuda_runtime.h>
#include <cstdint>

// AlignedLinear: y[n, o*9+d] = alpha * sum_i x[n, i*9+d] * K[r(d), i, o]
// r(d) = 0 for d=0, 1 for d in 1..3, 2 for d in 4..8.
// TF32 mma.sync path; X and K staged in SMEM as tf32 bits.

#define MT        32            // nodes per CTA
#define DIMT      9
#define MUL       128
#define ROWF      1152          // MUL*DIMT floats per node row
#define XS_STRIDE 1156          // ROWF + 4 (bank-conflict-free stride-9 reads)
#define KS_STRIDE 132           // MUL + 4
#define NTHREADS  256

static __device__ __forceinline__ uint32_t f2tf32(float f) {
    uint32_t u;
    asm("cvt.rna.tf32.f32 %0, %1;" : "=r"(u) : "f"(f));
    return u;
}

__global__ void __launch_bounds__(NTHREADS, 1)
aligned_linear_tf32(const float* __restrict__ x,
                    const float* __restrict__ kern,
                    float* __restrict__ y,
                    int n_nodes)
{
    extern __shared__ uint32_t smem[];
    uint32_t* sX = smem;                    // [MT][XS_STRIDE] tf32 bits
    uint32_t* sK = smem + MT * XS_STRIDE;   // [MUL][KS_STRIDE] tf32 bits

    const int tid  = threadIdx.x;
    const int lane = tid & 31;
    const int warp = tid >> 5;
    const int g    = lane >> 2;   // groupID 0..7
    const int tg   = lane & 3;    // thread-in-group 0..3
    const int wm   = (warp & 1) * 16;   // warp M offset: 0 / 16
    const int wn   = (warp >> 1) * 32;  // warp N offset: 0/32/64/96

    const long long node0 = (long long)blockIdx.x * MT;

    // ---- Stage X tile: [MT x 1152] fp32, coalesced float4, convert to tf32 ----
    #pragma unroll 4
    for (int it = tid; it < MT * (ROWF / 4); it += NTHREADS) {
        int row = it / (ROWF / 4);
        int c4  = it - row * (ROWF / 4);
        long long n = node0 + row;
        float4 v = make_float4(0.f, 0.f, 0.f, 0.f);
        if (n < (long long)n_nodes)
            v = *reinterpret_cast<const float4*>(x + n * ROWF + c4 * 4);
        uint32_t* dst = sX + row * XS_STRIDE + c4 * 4;
        dst[0] = f2tf32(v.x);
        dst[1] = f2tf32(v.y);
        dst[2] = f2tf32(v.z);
        dst[3] = f2tf32(v.w);
    }

    const float ALPHA = 0.08838834764831845f;  // sqrt(1/128)
    int cur_r = -1;

    #pragma unroll 1
    for (int d = 0; d < DIMT; ++d) {
        const int r = (d == 0) ? 0 : (d < 4 ? 1 : 2);
        if (r != cur_r) {
            // All warps reach this at the same d (r is a pure function of d),
            // so these barriers are uniformly executed.
            __syncthreads();
            const float4* kg =
                reinterpret_cast<const float4*>(kern + (size_t)r * MUL * MUL);
            #pragma unroll 4
            for (int it = tid; it < MUL * (MUL / 4); it += NTHREADS) {
                int row = it >> 5;     // / (MUL/4) = 32
                int c4  = it & 31;
                float4 v = kg[it];
                uint32_t* dst = sK + row * KS_STRIDE + c4 * 4;
                dst[0] = f2tf32(v.x);
                dst[1] = f2tf32(v.y);
                dst[2] = f2tf32(v.z);
                dst[3] = f2tf32(v.w);
            }
            __syncthreads();
            cur_r = r;
        }

        // ---- 32x128 (M x O) GEMM over K=128 for this d ----
        float c[4][4];
        #pragma unroll
        for (int nt = 0; nt < 4; ++nt) {
            c[nt][0] = 0.f; c[nt][1] = 0.f; c[nt][2] = 0.f; c[nt][3] = 0.f;
        }

        #pragma unroll 4
        for (int kk = 0; kk < MUL; kk += 8) {
            // A fragment (m16n8k8 tf32, row-major):
            //   a0:(g,   tg) a1:(g+8, tg) a2:(g, tg+4) a3:(g+8, tg+4)
            uint32_t a0 = sX[(wm + g    ) * XS_STRIDE + (kk + tg    ) * DIMT + d];
            uint32_t a1 = sX[(wm + g + 8) * XS_STRIDE + (kk + tg    ) * DIMT + d];
            uint32_t a2 = sX[(wm + g    ) * XS_STRIDE + (kk + tg + 4) * DIMT + d];
            uint32_t a3 = sX[(wm + g + 8) * XS_STRIDE + (kk + tg + 4) * DIMT + d];
            #pragma unroll
            for (int nt = 0; nt < 4; ++nt) {
                int o = wn + nt * 8 + g;
                // B fragment (col-major): b0:(k=tg, n=g) b1:(k=tg+4, n=g)
                uint32_t b0 = sK[(kk + tg    ) * KS_STRIDE + o];
                uint32_t b1 = sK[(kk + tg + 4) * KS_STRIDE + o];
                asm volatile(
                    "mma.sync.aligned.m16n8k8.row.col.f32.tf32.tf32.f32 "
                    "{%0,%1,%2,%3}, {%4,%5,%6,%7}, {%8,%9}, {%0,%1,%2,%3};"
                    : "+f"(c[nt][0]), "+f"(c[nt][1]),
                      "+f"(c[nt][2]), "+f"(c[nt][3])
                    : "r"(a0), "r"(a1), "r"(a2), "r"(a3),
                      "r"(b0), "r"(b1));
            }
        }

        // ---- Store: C layout c0:(g, 2tg) c1:(g, 2tg+1) c2:(g+8, 2tg) c3:(g+8, 2tg+1)
        long long n_lo = node0 + wm + g;
        long long n_hi = n_lo + 8;
        bool v_lo = n_lo < (long long)n_nodes;
        bool v_hi = n_hi < (long long)n_nodes;
        float* y_lo = y + n_lo * ROWF + d;
        float* y_hi = y + n_hi * ROWF + d;
        #pragma unroll
        for (int nt = 0; nt < 4; ++nt) {
            int col = (wn + nt * 8 + 2 * tg) * DIMT;
            if (v_lo) {
                y_lo[col       ] = ALPHA * c[nt][0];
                y_lo[col + DIMT] = ALPHA * c[nt][1];
            }
            if (v_hi) {
                y_hi[col       ] = ALPHA * c[nt][2];
                y_hi[col + DIMT] = ALPHA * c[nt][3];
            }
        }
    }
}

extern "C" void kernel_launch(void* const* d_in, const int* in_sizes, int n_in,
                              void* d_out, int out_size)
{
    const float* x = (const float*)d_in[0];
    const float* k = (const float*)d_in[1];
    float* y = (float*)d_out;
    int n_nodes = in_sizes[0] / ROWF;

    size_t smem_bytes = (size_t)(MT * XS_STRIDE + MUL * KS_STRIDE) * sizeof(uint32_t);
    cudaFuncSetAttribute(aligned_linear_tf32,
                         cudaFuncAttributeMaxDynamicSharedMemorySize,
                         (int)smem_bytes);

    int grid = (n_nodes + MT - 1) / MT;
    aligned_linear_tf32<<<grid, NTHREADS, smem_bytes>>>(x, k, y, n_nodes);
}

// round 4
// speedup vs baseline: 1.9219x; 1.9219x over previous
#include <cuda_runtime.h>
#include <cstdint>

// AlignedLinear: y[n, o*9+d] = alpha * sum_i x[n, i*9+d] * K[r(d), i, o]
// r(d) = 0 for d=0, 1 for d=1..3, 2 for d=4..8.
// TF32 mma.sync; X tile staged in SMEM, outputs overwrite X columns in place
// (column i*9+d is dead after irrep d), single coalesced store at the end.

#define MT        32            // nodes per CTA
#define DIMT      9
#define MUL       128
#define ROWF      1152          // MUL*DIMT floats per node row
#define XS        1156          // ROWF + 4  (stride-9 A reads conflict-free)
#define KS        136           // MUL + 8   (8 mod 32 -> B reads conflict-free)
#define NTHREADS  256
#define ALPHA_F   0.08838834764831845f  // sqrt(1/128)

static __device__ __forceinline__ uint32_t f2tf32(float f) {
    uint32_t u;
    asm("cvt.rna.tf32.f32 %0, %1;" : "=r"(u) : "f"(f));
    return u;
}

static __device__ __forceinline__ void mma_tf32(float c[4],
    uint32_t a0, uint32_t a1, uint32_t a2, uint32_t a3,
    uint32_t b0, uint32_t b1)
{
    asm volatile(
        "mma.sync.aligned.m16n8k8.row.col.f32.tf32.tf32.f32 "
        "{%0,%1,%2,%3}, {%4,%5,%6,%7}, {%8,%9}, {%0,%1,%2,%3};"
        : "+f"(c[0]), "+f"(c[1]), "+f"(c[2]), "+f"(c[3])
        : "r"(a0), "r"(a1), "r"(a2), "r"(a3), "r"(b0), "r"(b1));
}

// One irrep group: stage K_R, GEMM all DC dims of this irrep accumulating over
// k, then write alpha*C back into sX (overwriting the now-dead X columns).
template<int R, int D0, int DC>
static __device__ __forceinline__ void process_group(
    uint32_t* __restrict__ sX, uint32_t* __restrict__ sK,
    const float* __restrict__ kern,
    int tid, int g, int tg, int wm, int wn)
{
    __syncthreads();   // prior reads of sK (and sX dims of previous group) done
    {
        const float4* kg =
            reinterpret_cast<const float4*>(kern + (size_t)R * MUL * MUL);
        #pragma unroll 4
        for (int it = tid; it < MUL * (MUL / 4); it += NTHREADS) {
            int row = it >> 5;
            int c4  = it & 31;
            float4 v = kg[it];
            uint32_t* dst = sK + row * KS + c4 * 4;
            dst[0] = f2tf32(v.x);
            dst[1] = f2tf32(v.y);
            dst[2] = f2tf32(v.z);
            dst[3] = f2tf32(v.w);
        }
    }
    __syncthreads();

    float c[DC][4][4];
    #pragma unroll
    for (int dd = 0; dd < DC; ++dd)
        #pragma unroll
        for (int nt = 0; nt < 4; ++nt)
            #pragma unroll
            for (int i = 0; i < 4; ++i) c[dd][nt][i] = 0.f;

    #pragma unroll 1
    for (int kk = 0; kk < MUL; kk += 8) {
        // B fragments: shared across all DC dims of this irrep
        uint32_t b[4][2];
        #pragma unroll
        for (int nt = 0; nt < 4; ++nt) {
            int o = wn + nt * 8 + g;
            b[nt][0] = sK[(kk + tg    ) * KS + o];
            b[nt][1] = sK[(kk + tg + 4) * KS + o];
        }
        #pragma unroll
        for (int dd = 0; dd < DC; ++dd) {
            const int d = D0 + dd;
            uint32_t a0 = sX[(wm + g    ) * XS + (kk + tg    ) * DIMT + d];
            uint32_t a1 = sX[(wm + g + 8) * XS + (kk + tg    ) * DIMT + d];
            uint32_t a2 = sX[(wm + g    ) * XS + (kk + tg + 4) * DIMT + d];
            uint32_t a3 = sX[(wm + g + 8) * XS + (kk + tg + 4) * DIMT + d];
            #pragma unroll
            for (int nt = 0; nt < 4; ++nt)
                mma_tf32(c[dd][nt], a0, a1, a2, a3, b[nt][0], b[nt][1]);
        }
    }

    __syncthreads();   // all warps finished reading X columns of this irrep

    // Overwrite the dead X columns with alpha*C (same column indices o*9+d).
    #pragma unroll
    for (int dd = 0; dd < DC; ++dd) {
        const int d = D0 + dd;
        #pragma unroll
        for (int nt = 0; nt < 4; ++nt) {
            int o = wn + nt * 8 + 2 * tg;
            uint32_t* lo = sX + (wm + g    ) * XS + o * DIMT + d;
            uint32_t* hi = sX + (wm + g + 8) * XS + o * DIMT + d;
            lo[0]    = __float_as_uint(ALPHA_F * c[dd][nt][0]);
            lo[DIMT] = __float_as_uint(ALPHA_F * c[dd][nt][1]);
            hi[0]    = __float_as_uint(ALPHA_F * c[dd][nt][2]);
            hi[DIMT] = __float_as_uint(ALPHA_F * c[dd][nt][3]);
        }
    }
}

__global__ void __launch_bounds__(NTHREADS, 1)
aligned_linear_tf32(const float* __restrict__ x,
                    const float* __restrict__ kern,
                    float* __restrict__ y,
                    int n_nodes)
{
    extern __shared__ uint32_t smem[];
    uint32_t* sX = smem;               // [MT][XS]  X tile -> becomes Y tile
    uint32_t* sK = smem + MT * XS;     // [MUL][KS] current irrep weights

    const int tid  = threadIdx.x;
    const int lane = tid & 31;
    const int warp = tid >> 5;
    const int g    = lane >> 2;
    const int tg   = lane & 3;
    const int wm   = (warp & 1) * 16;
    const int wn   = (warp >> 1) * 32;

    const long long node0 = (long long)blockIdx.x * MT;

    // ---- Stage X tile: coalesced float4 loads, convert to tf32 ----
    #pragma unroll 4
    for (int it = tid; it < MT * (ROWF / 4); it += NTHREADS) {
        int row = it / (ROWF / 4);
        int c4  = it - row * (ROWF / 4);
        long long n = node0 + row;
        float4 v = make_float4(0.f, 0.f, 0.f, 0.f);
        if (n < (long long)n_nodes)
            v = *reinterpret_cast<const float4*>(x + n * ROWF + c4 * 4);
        uint32_t* dst = sX + row * XS + c4 * 4;
        dst[0] = f2tf32(v.x);
        dst[1] = f2tf32(v.y);
        dst[2] = f2tf32(v.z);
        dst[3] = f2tf32(v.w);
    }

    process_group<0, 0, 1>(sX, sK, kern, tid, g, tg, wm, wn);
    process_group<1, 1, 3>(sX, sK, kern, tid, g, tg, wm, wn);
    process_group<2, 4, 5>(sX, sK, kern, tid, g, tg, wm, wn);

    __syncthreads();   // all writebacks visible

    // ---- Single coalesced store of the whole output tile ----
    #pragma unroll 4
    for (int it = tid; it < MT * (ROWF / 4); it += NTHREADS) {
        int row = it / (ROWF / 4);
        int c4  = it - row * (ROWF / 4);
        long long n = node0 + row;
        if (n < (long long)n_nodes) {
            const uint32_t* src = sX + row * XS + c4 * 4;
            float4 v;
            v.x = __uint_as_float(src[0]);
            v.y = __uint_as_float(src[1]);
            v.z = __uint_as_float(src[2]);
            v.w = __uint_as_float(src[3]);
            *reinterpret_cast<float4*>(y + n * ROWF + c4 * 4) = v;
        }
    }
}

extern "C" void kernel_launch(void* const* d_in, const int* in_sizes, int n_in,
                              void* d_out, int out_size)
{
    const float* x = (const float*)d_in[0];
    const float* k = (const float*)d_in[1];
    float* y = (float*)d_out;
    int n_nodes = in_sizes[0] / ROWF;

    size_t smem_bytes = (size_t)(MT * XS + MUL * KS) * sizeof(uint32_t);
    cudaFuncSetAttribute(aligned_linear_tf32,
                         cudaFuncAttributeMaxDynamicSharedMemorySize,
                         (int)smem_bytes);

    int grid = (n_nodes + MT - 1) / MT;
    aligned_linear_tf32<<<grid, NTHREADS, smem_bytes>>>(x, k, y, n_nodes);
}